// round 16
// baseline (speedup 1.0000x reference)
#include <cuda_runtime.h>
#include <cstdint>

// Problem constants (fixed by the dataset)
#define NN 100000
#define NE 1600000
#define F  32

// Scratch — layout IDENTICAL to the measured-best R9/R15 kernel (the aggregate
// gather loop is layout-sensitive; R14's extra array regressed it 2.5x).
__device__ int           g_cnt[NN];          // in-degree (excl. self-loop)
__device__ int           g_start[NN];        // packed bin start offsets
__device__ unsigned char g_relpos[NE];       // slot within dst bin (max deg << 255)
__device__ int           g_ebin[NE];         // src ids grouped by dst (packed)
__device__ int           g_total;            // global bin allocator
__device__ float         g_h[(size_t)NN * F];// projected features

// ---------------------------------------------------------------------------
// Kernel 1: zero counters (kept separate: folding resets anywhere near the
// aggregate path regressed 3-12x in R8/R11/R12/R14)
// ---------------------------------------------------------------------------
__global__ void k_zero(int n) {
    int i = blockIdx.x * blockDim.x + threadIdx.x;
    if (i < n) g_cnt[i] = 0;
    if (i == 0) g_total = 0;
}

// ---------------------------------------------------------------------------
// Kernel 2: histogram of dst; keep returned slot (byte) so fill is atomic-free
// ---------------------------------------------------------------------------
__global__ void k_hist(const int* __restrict__ dst, int e) {
    int i = blockIdx.x * blockDim.x + threadIdx.x;
    if (i < e) {
        int d = __ldg(dst + i);
        g_relpos[i] = (unsigned char)atomicAdd(&g_cnt[d], 1);
    }
}

// ---------------------------------------------------------------------------
// Kernel 3: packed-bin allocation — warp scan + one global atomic per warp.
// ---------------------------------------------------------------------------
__global__ void k_alloc(int n) {
    int t = blockIdx.x * blockDim.x + threadIdx.x;
    int lane = t & 31;
    int c = (t < n) ? g_cnt[t] : 0;

    int inc = c;
#pragma unroll
    for (int off = 1; off < 32; off <<= 1) {
        int tmp = __shfl_up_sync(0xFFFFFFFFu, inc, off);
        if (lane >= off) inc += tmp;
    }
    int excl = inc - c;
    int base = 0;
    if (lane == 31) base = atomicAdd(&g_total, inc);
    base = __shfl_sync(0xFFFFFFFFu, base, 31);
    if (t < n) g_start[t] = base + excl;
}

// ---------------------------------------------------------------------------
// Kernel 4 (heterogeneous blocks): first nproj blocks run WARP-PER-NODE
// shuffle PROJECTION (register-thin: ~20 regs, vs 66 for the R15
// thread-per-node version which throttled fill occupancy to 32%); remaining
// blocks run the bin FILL. Independent data paths -> they overlap in one
// launch.
//   projection: lane l of the node's warp computes
//       h[v][l] = sum_i (x[v][i]*s) * W[l][i]
//   via xv broadcast shuffles and W^T staged in padded shared memory
//   (sWt[i][l], stride 33 -> conflict-free reads).
// ---------------------------------------------------------------------------
__global__ void __launch_bounds__(256, 8) k_projfill(
        const float* __restrict__ x,
        const float* __restrict__ W,
        const int* __restrict__ src,
        const int* __restrict__ dst,
        int n, int e, int nproj) {
    if ((int)blockIdx.x < nproj) {
        // ---- warp-per-node projection ----
        __shared__ float sWt[F][F + 1];
        for (int idx = threadIdx.x; idx < F * F; idx += blockDim.x) {
            int o = idx >> 5;        // output row of W
            int i = idx & 31;        // input col
            sWt[i][o] = W[idx];
        }
        __syncthreads();

        int t = blockIdx.x * blockDim.x + threadIdx.x;
        int v = t >> 5;
        int lane = t & 31;
        if (v >= n) return;

        float s = rsqrtf((float)(g_cnt[v] + 1));
        float xv = __ldg(x + (size_t)v * F + lane) * s;

        float acc = 0.0f;
#pragma unroll
        for (int i = 0; i < F; i++) {
            float xi = __shfl_sync(0xFFFFFFFFu, xv, i);
            acc = fmaf(xi, sWt[i][lane], acc);
        }
        g_h[(size_t)v * F + lane] = acc;
    } else {
        // ---- fill: ebin[start[dst] + relpos] = src ----
        int i = (blockIdx.x - nproj) * blockDim.x + threadIdx.x;
        if (i >= e) return;
        int d = __ldg(dst + i);
        g_ebin[__ldg(g_start + d) + (int)g_relpos[i]] = __ldg(src + i);
    }
}

// ---------------------------------------------------------------------------
// Kernel 5: FULL warp per node gather + fused epilogue. BYTE-IDENTICAL to the
// measured-best aggregate: warp-uniform ebin broadcast loads, unroll 8,
// __ldg everywhere, reads g_start+g_cnt, READ-ONLY except `out`.
// ---------------------------------------------------------------------------
__global__ void k_aggregate(const float* __restrict__ bias,
                            float* __restrict__ out, int n) {
    int t = blockIdx.x * blockDim.x + threadIdx.x;
    int v = t >> 5;
    int lane = t & 31;
    if (v >= n) return;

    int start = g_start[v];
    int cnt = g_cnt[v];
    int end = start + cnt;

    float acc = g_h[(size_t)v * F + lane];   // self-loop contribution

    int i = start;
    for (; i + 8 <= end; i += 8) {
        int s0 = __ldg(g_ebin + i + 0);
        int s1 = __ldg(g_ebin + i + 1);
        int s2 = __ldg(g_ebin + i + 2);
        int s3 = __ldg(g_ebin + i + 3);
        int s4 = __ldg(g_ebin + i + 4);
        int s5 = __ldg(g_ebin + i + 5);
        int s6 = __ldg(g_ebin + i + 6);
        int s7 = __ldg(g_ebin + i + 7);
        float a0 = __ldg(g_h + (size_t)s0 * F + lane);
        float a1 = __ldg(g_h + (size_t)s1 * F + lane);
        float a2 = __ldg(g_h + (size_t)s2 * F + lane);
        float a3 = __ldg(g_h + (size_t)s3 * F + lane);
        float a4 = __ldg(g_h + (size_t)s4 * F + lane);
        float a5 = __ldg(g_h + (size_t)s5 * F + lane);
        float a6 = __ldg(g_h + (size_t)s6 * F + lane);
        float a7 = __ldg(g_h + (size_t)s7 * F + lane);
        acc += ((a0 + a1) + (a2 + a3)) + ((a4 + a5) + (a6 + a7));
    }
    for (; i + 2 <= end; i += 2) {
        int s0 = __ldg(g_ebin + i + 0);
        int s1 = __ldg(g_ebin + i + 1);
        float a0 = __ldg(g_h + (size_t)s0 * F + lane);
        float a1 = __ldg(g_h + (size_t)s1 * F + lane);
        acc += a0 + a1;
    }
    if (i < end) {
        int s = __ldg(g_ebin + i);
        acc += __ldg(g_h + (size_t)s * F + lane);
    }

    float r = rsqrtf((float)(cnt + 1));
    float b = __ldg(bias + lane);
    out[(size_t)v * F + lane] = fmaxf(fmaf(acc, r, b), 0.0f);
}

// ---------------------------------------------------------------------------
// Launch
// Inputs (metadata order): feature [N*32 f32], src [E i32], dst [E i32],
//                          W [32*32 f32], bias [32 f32]
// Output: [N*32] f32
// ---------------------------------------------------------------------------
extern "C" void kernel_launch(void* const* d_in, const int* in_sizes, int n_in,
                              void* d_out, int out_size) {
    const float* feature = (const float*)d_in[0];
    const int*   src     = (const int*)d_in[1];
    const int*   dst     = (const int*)d_in[2];
    const float* W       = (const float*)d_in[3];
    const float* bias    = (const float*)d_in[4];
    float*       out     = (float*)d_out;

    int n = in_sizes[0] / F;   // 100000
    int e = in_sizes[1];       // 1600000

    const int B = 256;

    k_zero<<<(n + B - 1) / B, B>>>(n);
    k_hist<<<(e + B - 1) / B, B>>>(dst, e);
    k_alloc<<<(n + B - 1) / B, B>>>(n);

    // warp-per-node projection: n*32 threads
    long long pthreads = (long long)n * 32;
    int nproj = (int)((pthreads + B - 1) / B);   // 12500 projection blocks
    int nfill = (e + B - 1) / B;                 // 6250 fill blocks
    k_projfill<<<nproj + nfill, B>>>(feature, W, src, dst, n, e, nproj);

    long long athreads = (long long)n * 32;
    int agg_blocks = (int)((athreads + B - 1) / B);
    k_aggregate<<<agg_blocks, B>>>(bias, out, n);
}

// round 17
// speedup vs baseline: 1.0541x; 1.0541x over previous
#include <cuda_runtime.h>
#include <cstdint>

// Problem constants (fixed by the dataset)
#define NN 100000
#define NE 1600000
#define F  32

// Scratch — layout IDENTICAL to the measured-best R9/R15 kernel (the aggregate
// gather loop is layout-sensitive; R14's extra array regressed it 2.5x).
__device__ int           g_cnt[NN];          // in-degree (excl. self-loop)
__device__ int           g_start[NN];        // packed bin start offsets
__device__ unsigned char g_relpos[NE];       // slot within dst bin (max deg << 255)
__device__ int           g_ebin[NE];         // src ids grouped by dst (packed)
__device__ int           g_total;            // global bin allocator
__device__ float         g_h[(size_t)NN * F];// projected features

// ---------------------------------------------------------------------------
// Kernel 1: zero counters (kept separate: folding resets anywhere near the
// aggregate path regressed 3-12x in R8/R11/R12/R14)
// ---------------------------------------------------------------------------
__global__ void k_zero(int n) {
    int i = blockIdx.x * blockDim.x + threadIdx.x;
    if (i < n) g_cnt[i] = 0;
    if (i == 0) g_total = 0;
}

// ---------------------------------------------------------------------------
// Kernel 2: histogram of dst; keep returned slot (byte) so fill is atomic-free
// ---------------------------------------------------------------------------
__global__ void k_hist(const int* __restrict__ dst, int e) {
    int i = blockIdx.x * blockDim.x + threadIdx.x;
    if (i < e) {
        int d = __ldg(dst + i);
        g_relpos[i] = (unsigned char)atomicAdd(&g_cnt[d], 1);
    }
}

// ---------------------------------------------------------------------------
// Kernel 3: packed-bin allocation — warp scan + one global atomic per warp.
// ---------------------------------------------------------------------------
__global__ void k_alloc(int n) {
    int t = blockIdx.x * blockDim.x + threadIdx.x;
    int lane = t & 31;
    int c = (t < n) ? g_cnt[t] : 0;

    int inc = c;
#pragma unroll
    for (int off = 1; off < 32; off <<= 1) {
        int tmp = __shfl_up_sync(0xFFFFFFFFu, inc, off);
        if (lane >= off) inc += tmp;
    }
    int excl = inc - c;
    int base = 0;
    if (lane == 31) base = atomicAdd(&g_total, inc);
    base = __shfl_sync(0xFFFFFFFFu, base, 31);
    if (t < n) g_start[t] = base + excl;
}

// ---------------------------------------------------------------------------
// Kernel 4 (heterogeneous blocks): first nproj blocks run THREAD-PER-NODE
// projection (the R15-proven dataflow — R16's shuffle variant was 1.4x
// slower), but register-thin: x is RE-LOADED from L1 per 8-output chunk
// instead of cached in xr[32] (regs 66 -> ~30, so the 6250 fill blocks in
// the same launch keep high occupancy). Remaining blocks run the bin FILL.
// ---------------------------------------------------------------------------
__global__ void __launch_bounds__(256, 8) k_projfill(
        const float* __restrict__ x,
        const float* __restrict__ W,
        const int* __restrict__ src,
        const int* __restrict__ dst,
        int n, int e, int nproj) {
    if ((int)blockIdx.x < nproj) {
        // ---- projection: h[v] = (x[v] * rsqrt(deg[v])) @ W^T ----
        __shared__ float sW[F][F];
        for (int i = threadIdx.x; i < F * F; i += blockDim.x)
            sW[i / F][i % F] = W[i];
        __syncthreads();

        int v = blockIdx.x * blockDim.x + threadIdx.x;
        if (v >= n) return;

        float s = rsqrtf((float)(g_cnt[v] + 1));
        const float4* xp = reinterpret_cast<const float4*>(x + (size_t)v * F);
        float4* hp = reinterpret_cast<float4*>(g_h + (size_t)v * F);

#pragma unroll 1
        for (int chunk = 0; chunk < 4; chunk++) {
            float acc[8];
#pragma unroll
            for (int o = 0; o < 8; o++) acc[o] = 0.0f;
#pragma unroll
            for (int i4 = 0; i4 < 8; i4++) {
                float4 q = __ldg(xp + i4);   // L1-hot after chunk 0
                float xs;
                xs = q.x * s;
#pragma unroll
                for (int o = 0; o < 8; o++)
                    acc[o] = fmaf(xs, sW[chunk * 8 + o][i4 * 4 + 0], acc[o]);
                xs = q.y * s;
#pragma unroll
                for (int o = 0; o < 8; o++)
                    acc[o] = fmaf(xs, sW[chunk * 8 + o][i4 * 4 + 1], acc[o]);
                xs = q.z * s;
#pragma unroll
                for (int o = 0; o < 8; o++)
                    acc[o] = fmaf(xs, sW[chunk * 8 + o][i4 * 4 + 2], acc[o]);
                xs = q.w * s;
#pragma unroll
                for (int o = 0; o < 8; o++)
                    acc[o] = fmaf(xs, sW[chunk * 8 + o][i4 * 4 + 3], acc[o]);
            }
            hp[chunk * 2 + 0] = make_float4(acc[0], acc[1], acc[2], acc[3]);
            hp[chunk * 2 + 1] = make_float4(acc[4], acc[5], acc[6], acc[7]);
        }
    } else {
        // ---- fill: ebin[start[dst] + relpos] = src ----
        int i = (blockIdx.x - nproj) * blockDim.x + threadIdx.x;
        if (i >= e) return;
        int d = __ldg(dst + i);
        g_ebin[__ldg(g_start + d) + (int)g_relpos[i]] = __ldg(src + i);
    }
}

// ---------------------------------------------------------------------------
// Kernel 5: FULL warp per node gather + fused epilogue. BYTE-IDENTICAL to the
// measured-best aggregate: warp-uniform ebin broadcast loads, unroll 8,
// __ldg everywhere, reads g_start+g_cnt, READ-ONLY except `out`.
// ---------------------------------------------------------------------------
__global__ void k_aggregate(const float* __restrict__ bias,
                            float* __restrict__ out, int n) {
    int t = blockIdx.x * blockDim.x + threadIdx.x;
    int v = t >> 5;
    int lane = t & 31;
    if (v >= n) return;

    int start = g_start[v];
    int cnt = g_cnt[v];
    int end = start + cnt;

    float acc = g_h[(size_t)v * F + lane];   // self-loop contribution

    int i = start;
    for (; i + 8 <= end; i += 8) {
        int s0 = __ldg(g_ebin + i + 0);
        int s1 = __ldg(g_ebin + i + 1);
        int s2 = __ldg(g_ebin + i + 2);
        int s3 = __ldg(g_ebin + i + 3);
        int s4 = __ldg(g_ebin + i + 4);
        int s5 = __ldg(g_ebin + i + 5);
        int s6 = __ldg(g_ebin + i + 6);
        int s7 = __ldg(g_ebin + i + 7);
        float a0 = __ldg(g_h + (size_t)s0 * F + lane);
        float a1 = __ldg(g_h + (size_t)s1 * F + lane);
        float a2 = __ldg(g_h + (size_t)s2 * F + lane);
        float a3 = __ldg(g_h + (size_t)s3 * F + lane);
        float a4 = __ldg(g_h + (size_t)s4 * F + lane);
        float a5 = __ldg(g_h + (size_t)s5 * F + lane);
        float a6 = __ldg(g_h + (size_t)s6 * F + lane);
        float a7 = __ldg(g_h + (size_t)s7 * F + lane);
        acc += ((a0 + a1) + (a2 + a3)) + ((a4 + a5) + (a6 + a7));
    }
    for (; i + 2 <= end; i += 2) {
        int s0 = __ldg(g_ebin + i + 0);
        int s1 = __ldg(g_ebin + i + 1);
        float a0 = __ldg(g_h + (size_t)s0 * F + lane);
        float a1 = __ldg(g_h + (size_t)s1 * F + lane);
        acc += a0 + a1;
    }
    if (i < end) {
        int s = __ldg(g_ebin + i);
        acc += __ldg(g_h + (size_t)s * F + lane);
    }

    float r = rsqrtf((float)(cnt + 1));
    float b = __ldg(bias + lane);
    out[(size_t)v * F + lane] = fmaxf(fmaf(acc, r, b), 0.0f);
}

// ---------------------------------------------------------------------------
// Launch
// Inputs (metadata order): feature [N*32 f32], src [E i32], dst [E i32],
//                          W [32*32 f32], bias [32 f32]
// Output: [N*32] f32
// ---------------------------------------------------------------------------
extern "C" void kernel_launch(void* const* d_in, const int* in_sizes, int n_in,
                              void* d_out, int out_size) {
    const float* feature = (const float*)d_in[0];
    const int*   src     = (const int*)d_in[1];
    const int*   dst     = (const int*)d_in[2];
    const float* W       = (const float*)d_in[3];
    const float* bias    = (const float*)d_in[4];
    float*       out     = (float*)d_out;

    int n = in_sizes[0] / F;   // 100000
    int e = in_sizes[1];       // 1600000

    const int B = 256;

    k_zero<<<(n + B - 1) / B, B>>>(n);
    k_hist<<<(e + B - 1) / B, B>>>(dst, e);
    k_alloc<<<(n + B - 1) / B, B>>>(n);

    int nproj = (n + B - 1) / B;           // 391 projection blocks
    int nfill = (e + B - 1) / B;           // 6250 fill blocks
    k_projfill<<<nproj + nfill, B>>>(feature, W, src, dst, n, e, nproj);

    long long athreads = (long long)n * 32;
    int agg_blocks = (int)((athreads + B - 1) / B);
    k_aggregate<<<agg_blocks, B>>>(bias, out, n);
}